// round 2
// baseline (speedup 1.0000x reference)
#include <cuda_runtime.h>
#include <cstdint>
#include <cstddef>

#define BB 64
#define TT 512
#define EE 256
#define HH 256
#define LLB 9
#define G4 1024   // 4*H

// Scratch (device globals; no allocations allowed)
__device__ float g_xg[(size_t)2*TT*G4*BB];   // [dir][t][col][b]  256 MiB
__device__ float g_h [(size_t)2*TT*HH*BB];   // [dir][t][u][b]     16 MiB
__device__ int   g_seqlen[BB];
__device__ unsigned g_bar[2];                // {count, generation}

__device__ __forceinline__ float sigf(float x){
    return __fdividef(1.f, 1.f + __expf(-x));
}
__device__ __forceinline__ float tanhfast(float x){
    return 1.f - __fdividef(2.f, __expf(2.f*x) + 1.f);
}

// ---------------------------------------------------------------- seq_len
__global__ void k_seqlen(const int* __restrict__ tokens, float* __restrict__ out_seq){
    int b = blockIdx.x, tid = threadIdx.x;
    int cnt = 0;
    for (int t = tid; t < TT; t += blockDim.x)
        cnt += (tokens[b*TT + t] != 0);
    __shared__ int sred[128];
    sred[tid] = cnt; __syncthreads();
    for (int s = 64; s > 0; s >>= 1){
        if (tid < s) sred[tid] += sred[tid+s];
        __syncthreads();
    }
    if (tid == 0){ g_seqlen[b] = sred[0]; out_seq[b] = (float)sred[0]; }
}

// ---------------------------------------------------------------- barrier init
__global__ void k_init(){
    if (threadIdx.x == 0){ g_bar[0] = 0u; g_bar[1] = 0u; }
}

// ---------------------------------------------------------------- xg GEMM
// C[t, col, b] = sum_k emb[tokens[b,t], k] * Wx[k, col] + bias[col]
// grid: (512 t, 32 col-tiles[16 fwd + 16 bwd]), block 256
__global__ void __launch_bounds__(256) k_xg(
    const int* __restrict__ tokens, const float* __restrict__ emb,
    const float* __restrict__ Wxf, const float* __restrict__ bf,
    const float* __restrict__ Wxb, const float* __restrict__ bb_)
{
    extern __shared__ float sm[];
    float* As = sm;            // [256 k][64 b]
    float* Ws = sm + 256*64;   // [256 k][64 c]
    __shared__ int toks[64];

    int t    = blockIdx.x;
    int ct   = blockIdx.y;
    int dir  = ct >> 4;
    int col0 = (ct & 15) * 64;
    const float* Wx   = dir ? Wxb : Wxf;
    const float* bias = dir ? bb_ : bf;
    int tid = threadIdx.x;

    if (tid < 64) toks[tid] = tokens[tid*TT + t];
    __syncthreads();

    // gather A (emb rows), store k-major for conflict-free reads
    for (int i = tid; i < 64*64; i += 256){
        int b = i & 63, k4 = i >> 6;
        float4 v = *(const float4*)(emb + (size_t)toks[b]*EE + k4*4);
        As[(k4*4+0)*64 + b] = v.x;
        As[(k4*4+1)*64 + b] = v.y;
        As[(k4*4+2)*64 + b] = v.z;
        As[(k4*4+3)*64 + b] = v.w;
    }
    for (int i = tid; i < 4096; i += 256){
        int k = i >> 4, c4 = i & 15;
        float4 v = *(const float4*)(Wx + (size_t)k*G4 + col0 + c4*4);
        *(float4*)(Ws + k*64 + c4*4) = v;
    }
    __syncthreads();

    int tx = tid & 15, ty = tid >> 4;
    float acc[4][4];
    #pragma unroll
    for (int j = 0; j < 4; ++j){
        float bv = bias[col0 + tx*4 + j];
        acc[0][j] = bv; acc[1][j] = bv; acc[2][j] = bv; acc[3][j] = bv;
    }
    #pragma unroll 4
    for (int k = 0; k < 256; ++k){
        float4 w = *(const float4*)(Ws + k*64 + tx*4);
        float a0 = As[k*64 + ty];
        float a1 = As[k*64 + ty + 16];
        float a2 = As[k*64 + ty + 32];
        float a3 = As[k*64 + ty + 48];
        acc[0][0] += a0*w.x; acc[0][1] += a0*w.y; acc[0][2] += a0*w.z; acc[0][3] += a0*w.w;
        acc[1][0] += a1*w.x; acc[1][1] += a1*w.y; acc[1][2] += a1*w.z; acc[1][3] += a1*w.w;
        acc[2][0] += a2*w.x; acc[2][1] += a2*w.y; acc[2][2] += a2*w.z; acc[2][3] += a2*w.w;
        acc[3][0] += a3*w.x; acc[3][1] += a3*w.y; acc[3][2] += a3*w.z; acc[3][3] += a3*w.w;
    }
    size_t xbase = ((size_t)dir*TT + t) * (size_t)(G4*BB);
    #pragma unroll
    for (int bi = 0; bi < 4; ++bi){
        int b = ty + bi*16;
        #pragma unroll
        for (int j = 0; j < 4; ++j){
            int col = col0 + tx*4 + j;
            g_xg[xbase + (size_t)col*BB + b] = acc[bi][j];
        }
    }
}

// ---------------------------------------------------------------- recurrence
__device__ __forceinline__ void grid_barrier(unsigned expected){
    __threadfence();
    __syncthreads();
    if (threadIdx.x == 0){
        volatile unsigned* vgen = (volatile unsigned*)&g_bar[1];
        unsigned gen = *vgen;
        unsigned old = atomicAdd(&g_bar[0], 1u);
        if (old == expected - 1u){
            atomicExch(&g_bar[0], 0u);
            __threadfence();
            atomicAdd(&g_bar[1], 1u);
        } else {
            while (*vgen == gen) { }
        }
    }
    __syncthreads();
}

// 128 CTAs: [0,64) forward, [64,128) backward. CTA owns 4 hidden units.
// 256 threads: b = tid&63, ul = tid>>6. c-state lives in registers.
__global__ void __launch_bounds__(256) k_recur(
    const float* __restrict__ Whf, const float* __restrict__ Whb)
{
    extern __shared__ float sm[];
    float* hs  = sm;             // [256 k][64 b]
    float* Whs = sm + 256*64;    // [256 k][4 ul][4 g]

    int cta = blockIdx.x;
    int dir = cta >> 6;
    int u0  = (cta & 63) * 4;
    const float* Wh = dir ? Whb : Whf;
    int tid = threadIdx.x;
    int b  = tid & 63;
    int ul = tid >> 6;
    int u  = u0 + ul;

    for (int i = tid; i < 4096; i += 256){
        int k = i >> 4, q = i & 15;
        int ulx = q >> 2, g = q & 3;
        Whs[i] = Wh[(size_t)k*G4 + g*HH + u0 + ulx];
    }
    __syncthreads();

    float c = 0.f;
    size_t hdir = (size_t)dir * TT * HH * BB;

    for (int step = 0; step < TT; ++step){
        int t = dir ? (TT-1-step) : step;
        float acc0 = 0.f, acc1 = 0.f, acc2 = 0.f, acc3 = 0.f;

        if (step > 0){
            int tp = dir ? (t+1) : (t-1);
            const float4* src = (const float4*)(g_h + hdir + (size_t)tp*HH*BB);
            float4* dst = (float4*)hs;
            #pragma unroll
            for (int i = 0; i < 16; ++i) dst[tid + 256*i] = src[tid + 256*i];
            __syncthreads();
            #pragma unroll 4
            for (int k = 0; k < HH; ++k){
                float hv = hs[k*64 + b];
                float4 w = *(const float4*)(Whs + k*16 + ul*4);
                acc0 += hv*w.x; acc1 += hv*w.y; acc2 += hv*w.z; acc3 += hv*w.w;
            }
        }
        size_t xb = ((size_t)dir*TT + t) * (size_t)(G4*BB) + (size_t)u*BB + b;
        acc0 += g_xg[xb];
        acc1 += g_xg[xb + 1*HH*BB];
        acc2 += g_xg[xb + 2*HH*BB];
        acc3 += g_xg[xb + 3*HH*BB];

        float iv = sigf(acc0);
        float fv = sigf(acc1);
        float gv = tanhfast(acc2);
        float ov = sigf(acc3);
        c = fv*c + iv*gv;
        float h = ov * tanhfast(c);
        g_h[hdir + (size_t)t*HH*BB + (size_t)u*BB + b] = h;

        grid_barrier(128u);
    }
}

// ---------------------------------------------------------------- dense
// logits[b,t,l] = sum_k enc[b,t,k] * Wd[k,l] + bd[l] ; enc = [h_fwd | h_bwd]
__global__ void __launch_bounds__(576) k_dense(
    const float* __restrict__ Wd, const float* __restrict__ bd,
    float* __restrict__ out)
{
    extern __shared__ float sm[];
    float* hs  = sm;             // [512 k][64 b]
    float* Wds = sm + 512*64;    // [512 k][9 l]

    int t = blockIdx.x, tid = threadIdx.x;
    const float4* s0 = (const float4*)(g_h + (size_t)t*HH*BB);
    const float4* s1 = (const float4*)(g_h + (size_t)TT*HH*BB + (size_t)t*HH*BB);
    float4* d0 = (float4*)hs;
    for (int i = tid; i < 4096; i += 576) d0[i] = s0[i];
    for (int i = tid; i < 4096; i += 576) d0[4096 + i] = s1[i];
    for (int i = tid; i < 512*LLB; i += 576) Wds[i] = Wd[i];
    __syncthreads();

    int b = tid / LLB;
    int l = tid - b*LLB;
    float acc = bd[l];
    #pragma unroll 4
    for (int k = 0; k < 512; ++k)
        acc += hs[k*64 + b] * Wds[k*LLB + l];
    out[((size_t)b*TT + t)*LLB + l] = acc;
}

// ---------------------------------------------------------------- CRF
__global__ void k_crf(const int* __restrict__ labels, const float* __restrict__ trans,
                      const float* __restrict__ logits, float* __restrict__ out_ll)
{
    int b = blockIdx.x;
    int j = threadIdx.x;   // 32 lanes, lanes 0..8 active for alpha
    int sl = g_seqlen[b];
    const float* lg = logits + (size_t)b*TT*LLB;
    const int*   tg = labels + (size_t)b*TT;

    // gold score
    float sc = 0.f;
    for (int t = j; t < TT; t += 32){
        if (t < sl){
            sc += lg[t*LLB + tg[t]];
            if (t >= 1) sc += trans[tg[t-1]*LLB + tg[t]];
        }
    }
    #pragma unroll
    for (int o = 16; o > 0; o >>= 1) sc += __shfl_xor_sync(0xffffffffu, sc, o);

    // alpha recursion
    float trj[9];
    if (j < 9){
        #pragma unroll
        for (int i = 0; i < 9; ++i) trj[i] = trans[i*LLB + j];
    }
    float a[9];
    #pragma unroll
    for (int i = 0; i < 9; ++i) a[i] = lg[i];

    __shared__ float sa[9];
    int tmax = (sl < TT) ? sl : TT;
    for (int t = 1; t < tmax; ++t){
        if (j < 9){
            float lgt = lg[t*LLB + j];
            float v[9]; float m = -1e30f;
            #pragma unroll
            for (int i = 0; i < 9; ++i){ v[i] = a[i] + trj[i]; m = fmaxf(m, v[i]); }
            float s = 0.f;
            #pragma unroll
            for (int i = 0; i < 9; ++i) s += __expf(v[i] - m);
            sa[j] = m + __logf(s) + lgt;
        }
        __syncwarp();
        #pragma unroll
        for (int i = 0; i < 9; ++i) a[i] = sa[i];
        __syncwarp();
    }

    if (j == 0){
        float m = a[0];
        #pragma unroll
        for (int i = 1; i < 9; ++i) m = fmaxf(m, a[i]);
        float s = 0.f;
        #pragma unroll
        for (int i = 0; i < 9; ++i) s += __expf(a[i] - m);
        out_ll[b] = sc - (m + __logf(s));
    }
}

// ---------------------------------------------------------------- launch
extern "C" void kernel_launch(void* const* d_in, const int* in_sizes, int n_in,
                              void* d_out, int out_size)
{
    const int*   tokens = (const int*)  d_in[0];
    const int*   labels = (const int*)  d_in[1];
    const float* emb    = (const float*)d_in[2];
    const float* Wxf    = (const float*)d_in[3];
    const float* Whf    = (const float*)d_in[4];
    const float* bf     = (const float*)d_in[5];
    const float* Wxb    = (const float*)d_in[6];
    const float* Whb    = (const float*)d_in[7];
    const float* bb     = (const float*)d_in[8];
    const float* Wd     = (const float*)d_in[9];
    const float* bd     = (const float*)d_in[10];
    const float* trans  = (const float*)d_in[11];
    float* out = (float*)d_out;

    cudaFuncSetAttribute(k_xg,    cudaFuncAttributeMaxDynamicSharedMemorySize, 131072);
    cudaFuncSetAttribute(k_recur, cudaFuncAttributeMaxDynamicSharedMemorySize, 81920);
    cudaFuncSetAttribute(k_dense, cudaFuncAttributeMaxDynamicSharedMemorySize, 149504);

    const int LOGITS_N = BB*TT*LLB;   // 294912

    k_seqlen<<<BB, 128>>>(tokens, out + LOGITS_N);

    dim3 gx(TT, 32);
    k_xg<<<gx, 256, 131072>>>(tokens, emb, Wxf, bf, Wxb, bb);

    k_init<<<1, 32>>>();
    k_recur<<<128, 256, 81920>>>(Whf, Whb);

    k_dense<<<TT, 576, 149504>>>(Wd, bd, out);

    k_crf<<<BB, 32>>>(labels, trans, out, out + LOGITS_N + BB);
}